// round 12
// baseline (speedup 1.0000x reference)
#include <cuda_runtime.h>

// SAGE_69587060130174 — MaxK-GNN forward on GB300 (sm_103a), fp32 SIMT.
// R11: 8 rows/warp (halve weight-LDS per row; crossbar was the binder),
// A/pack via broadcast __ldg (no SMEM staging), base-clamp row handling.

static constexpr int NNODES = 50000;
static constexpr int NEDGES = 800000;
static constexpr int HIDDIM = 128;
static constexpr int OUTDIM = 64;
static constexpr int KTOP   = 32;

__device__ float  g_agg[(size_t)NNODES * HIDDIM];   // 25.6 MB
__device__ float2 g_pack[(size_t)NNODES * KTOP];    // 12.8 MB (.x=val,.y=idx bits)
__device__ float  g_deg[NNODES];

// monotonic float<->uint key (order-preserving bijection)
__device__ __forceinline__ unsigned f2key(float x) {
    unsigned k = __float_as_uint(x);
    return (k & 0x80000000u) ? ~k : (k | 0x80000000u);
}
__device__ __forceinline__ float key2f(unsigned k) {
    return __uint_as_float((k & 0x80000000u) ? (k & 0x7fffffffu) : ~k);
}

// ---------------------------------------------------------------------------
// Exact, stable top-32 of EIGHT warp-held 128-vectors (acc[r][q] = row r,
// col lane*4+q). 8 independent REDUX/ballot chains per round -> deep ILP.
// Tie-break = smallest flat column index — matches jax.lax.top_k.
__device__ __forceinline__ void warp_top32_x8(float acc[8][4], int lane,
                                              int base) {
    const float NEG = __int_as_float(0xff800000);  // -inf
    float2 out[8];
    for (int t = 0; t < 32; t++) {
        #pragma unroll
        for (int r = 0; r < 8; r++) {
            float lm = acc[r][0]; int lq = 0;
            if (acc[r][1] > lm) { lm = acc[r][1]; lq = 1; }
            if (acc[r][2] > lm) { lm = acc[r][2]; lq = 2; }
            if (acc[r][3] > lm) { lm = acc[r][3]; lq = 3; }
            unsigned key  = f2key(lm);
            unsigned wk   = __reduce_max_sync(0xffffffffu, key);
            unsigned ball = __ballot_sync(0xffffffffu, key == wk);
            int srcl = __ffs(ball) - 1;
            int wq   = __shfl_sync(0xffffffffu, lq, srcl);
            if (lane == srcl) {
                if      (lq == 0) acc[r][0] = NEG;
                else if (lq == 1) acc[r][1] = NEG;
                else if (lq == 2) acc[r][2] = NEG;
                else              acc[r][3] = NEG;
            }
            if (lane == t)
                out[r] = make_float2(key2f(wk), __int_as_float((srcl << 2) | wq));
        }
    }
    #pragma unroll
    for (int r = 0; r < 8; r++)
        g_pack[(size_t)(base + r) * KTOP + lane] = out[r];  // coalesced
}

// ---------------------------------------------------------------------------
__global__ void k_deg(const int* __restrict__ ei) {
    int stride = gridDim.x * blockDim.x;
    for (int e = blockIdx.x * blockDim.x + threadIdx.x; e < NEDGES; e += stride)
        atomicAdd(&g_deg[__ldg(ei + e)], 1.0f);
}

// ---------------------------------------------------------------------------
// lin_in + fused top32: pack = top32(A[N,128] @ W[128,128] + bias).
// 8 rows/warp; A via broadcast __ldg; only W in SMEM.
__global__ __launch_bounds__(512) void k_lin_in(const float* __restrict__ A,
                                                const float* __restrict__ W,
                                                const float* __restrict__ bias) {
    extern __shared__ float sm[];
    float* sW = sm;  // 16384 floats

    const int tid = threadIdx.x, warp = tid >> 5, lane = tid & 31;
    for (int i = tid; i < 4096; i += blockDim.x)
        ((float4*)sW)[i] = ((const float4*)W)[i];
    __syncthreads();

    int base = blockIdx.x * 128 + warp * 8;
    if (base > NNODES - 8) base = NNODES - 8;   // duplicates write same bytes

    float acc[8][4];
    {
        float4 bv = __ldg((const float4*)bias + lane);
        #pragma unroll
        for (int r = 0; r < 8; r++) {
            acc[r][0] = bv.x; acc[r][1] = bv.y; acc[r][2] = bv.z; acc[r][3] = bv.w;
        }
    }

    #pragma unroll 2
    for (int k4 = 0; k4 < 32; k4++) {
        float4 w0 = *(const float4*)&sW[(k4 * 4 + 0) * 128 + lane * 4];
        float4 w1 = *(const float4*)&sW[(k4 * 4 + 1) * 128 + lane * 4];
        float4 w2 = *(const float4*)&sW[(k4 * 4 + 2) * 128 + lane * 4];
        float4 w3 = *(const float4*)&sW[(k4 * 4 + 3) * 128 + lane * 4];
        #pragma unroll
        for (int r = 0; r < 8; r++) {
            float4 a = __ldg((const float4*)(A + (size_t)(base + r) * 128) + k4);
            acc[r][0] += a.x * w0.x; acc[r][1] += a.x * w0.y; acc[r][2] += a.x * w0.z; acc[r][3] += a.x * w0.w;
            acc[r][0] += a.y * w1.x; acc[r][1] += a.y * w1.y; acc[r][2] += a.y * w1.z; acc[r][3] += a.y * w1.w;
            acc[r][0] += a.z * w2.x; acc[r][1] += a.z * w2.y; acc[r][2] += a.z * w2.z; acc[r][3] += a.z * w2.w;
            acc[r][0] += a.w * w3.x; acc[r][1] += a.w * w3.y; acc[r][2] += a.w * w3.z; acc[r][3] += a.w * w3.w;
        }
    }

    warp_top32_x8(acc, lane, base);
}

// ---------------------------------------------------------------------------
// Edge scatter: one warp per edge; lane handles one of 32 nonzeros of hs[dst]
// (single coalesced float2 load) and atomically adds into agg[src].
__global__ __launch_bounds__(256) void k_scatter(const int* __restrict__ ei) {
    int gw = (blockIdx.x * blockDim.x + threadIdx.x) >> 5;
    if (gw >= NEDGES) return;
    int lane = threadIdx.x & 31;
    int s = __ldg(ei + gw);
    int d = __ldg(ei + NEDGES + gw);
    float2 p = g_pack[(size_t)d * KTOP + lane];
    float* ap = g_agg + (size_t)s * 128;
    atomicAdd(ap + __float_as_int(p.y), p.x);
}

// ---------------------------------------------------------------------------
// Fused layer: t = sparse(pack) @ W_self + (agg/(deg+1e-6)) @ W_neigh.
// MODE 0: pack = top32(t);   MODE 1: out = t @ W_out + b_out (fused lin_out).
// 8 rows/warp; agg + pack via broadcast __ldg; weights in SMEM.
// Dense term accumulated unscaled then *= inv (rounding diff ~1e-7).
template <int MODE>
__global__ __launch_bounds__(512) void k_layer(const float* __restrict__ Ws,
                                               const float* __restrict__ Wn,
                                               const float* __restrict__ Wo,
                                               const float* __restrict__ bo,
                                               float* __restrict__ out) {
    extern __shared__ float sm[];
    float* sWs = sm;            // 16384 floats
    float* sWn = sm + 16384;    // 16384 floats
    float* sWo = sm + 32768;    // 8192 floats  (MODE 1)
    float* sT  = sm + 40960;    // 16 warps * 1024 floats (MODE 1 restage)

    const int tid = threadIdx.x, warp = tid >> 5, lane = tid & 31;

    for (int i = tid; i < 4096; i += blockDim.x) {
        ((float4*)sWs)[i] = ((const float4*)Ws)[i];
        ((float4*)sWn)[i] = ((const float4*)Wn)[i];
    }
    if constexpr (MODE == 1) {
        for (int i = tid; i < 2048; i += blockDim.x)
            ((float4*)sWo)[i] = ((const float4*)Wo)[i];
    }
    __syncthreads();

    int base = blockIdx.x * 128 + warp * 8;
    if (base > NNODES - 8) base = NNODES - 8;   // duplicates write same bytes

    float inv[8];
    #pragma unroll
    for (int r = 0; r < 8; r++)
        inv[r] = 1.0f / (__ldg(&g_deg[base + r]) + 1e-6f);

    float acc[8][4] = {};

    // dense neighbor term (unscaled); weight rows shared across 8 rows
    #pragma unroll 2
    for (int k4 = 0; k4 < 32; k4++) {
        float4 w0 = *(const float4*)&sWn[(k4 * 4 + 0) * 128 + lane * 4];
        float4 w1 = *(const float4*)&sWn[(k4 * 4 + 1) * 128 + lane * 4];
        float4 w2 = *(const float4*)&sWn[(k4 * 4 + 2) * 128 + lane * 4];
        float4 w3 = *(const float4*)&sWn[(k4 * 4 + 3) * 128 + lane * 4];
        #pragma unroll
        for (int r = 0; r < 8; r++) {
            float4 a = __ldg((const float4*)(g_agg + (size_t)(base + r) * 128) + k4);
            acc[r][0] += a.x * w0.x; acc[r][1] += a.x * w0.y; acc[r][2] += a.x * w0.z; acc[r][3] += a.x * w0.w;
            acc[r][0] += a.y * w1.x; acc[r][1] += a.y * w1.y; acc[r][2] += a.y * w1.z; acc[r][3] += a.y * w1.w;
            acc[r][0] += a.z * w2.x; acc[r][1] += a.z * w2.y; acc[r][2] += a.z * w2.z; acc[r][3] += a.z * w2.w;
            acc[r][0] += a.w * w3.x; acc[r][1] += a.w * w3.y; acc[r][2] += a.w * w3.z; acc[r][3] += a.w * w3.w;
        }
    }
    #pragma unroll
    for (int r = 0; r < 8; r++) {
        acc[r][0] *= inv[r]; acc[r][1] *= inv[r];
        acc[r][2] *= inv[r]; acc[r][3] *= inv[r];
    }

    // sparse self-term: broadcast __ldg of pack (row's 256B L1-resident)
    #pragma unroll 4
    for (int t = 0; t < 32; t++) {
        #pragma unroll
        for (int r = 0; r < 8; r++) {
            float2 p = __ldg(&g_pack[(size_t)(base + r) * KTOP + t]);
            int j = __float_as_int(p.y);
            float4 w = *(const float4*)&sWs[j * 128 + lane * 4];
            acc[r][0] += p.x * w.x; acc[r][1] += p.x * w.y;
            acc[r][2] += p.x * w.z; acc[r][3] += p.x * w.w;
        }
    }

    if constexpr (MODE == 0) {
        warp_top32_x8(acc, lane, base);
    } else {
        // fused lin_out: restage acc rows into per-warp SMEM tile, then the
        // standard CPL=2 GEMM against sWo.
        float4* myT = (float4*)(sT + warp * 1024);
        #pragma unroll
        for (int r = 0; r < 8; r++)
            myT[r * 32 + lane] = make_float4(acc[r][0], acc[r][1], acc[r][2], acc[r][3]);
        __syncwarp();

        float acc2[8][2];
        {
            float2 bv = __ldg((const float2*)bo + lane);
            #pragma unroll
            for (int r = 0; r < 8; r++) { acc2[r][0] = bv.x; acc2[r][1] = bv.y; }
        }

        #pragma unroll 2
        for (int k4 = 0; k4 < 32; k4++) {
            float2 w0 = *(const float2*)&sWo[(k4 * 4 + 0) * 64 + lane * 2];
            float2 w1 = *(const float2*)&sWo[(k4 * 4 + 1) * 64 + lane * 2];
            float2 w2 = *(const float2*)&sWo[(k4 * 4 + 2) * 64 + lane * 2];
            float2 w3 = *(const float2*)&sWo[(k4 * 4 + 3) * 64 + lane * 2];
            #pragma unroll
            for (int r = 0; r < 8; r++) {
                float4 a = myT[r * 32 + k4];  // broadcast LDS
                acc2[r][0] += a.x * w0.x; acc2[r][1] += a.x * w0.y;
                acc2[r][0] += a.y * w1.x; acc2[r][1] += a.y * w1.y;
                acc2[r][0] += a.z * w2.x; acc2[r][1] += a.z * w2.y;
                acc2[r][0] += a.w * w3.x; acc2[r][1] += a.w * w3.y;
            }
        }

        #pragma unroll
        for (int r = 0; r < 8; r++) {
            float2 o = make_float2(acc2[r][0], acc2[r][1]);
            *reinterpret_cast<float2*>(&out[(size_t)(base + r) * OUTDIM + lane * 2]) = o;
        }
    }
}

// ---------------------------------------------------------------------------
extern "C" void kernel_launch(void* const* d_in, const int* in_sizes, int n_in,
                              void* d_out, int out_size) {
    const float* x       = (const float*)d_in[0];
    const float* W_in    = (const float*)d_in[1];
    const float* b_in    = (const float*)d_in[2];
    const float* W_self  = (const float*)d_in[3];
    const float* W_neigh = (const float*)d_in[4];
    const float* W_out   = (const float*)d_in[5];
    const float* b_out   = (const float*)d_in[6];
    const int*   ei      = (const int*)d_in[7];
    float* out = (float*)d_out;
    (void)in_sizes; (void)n_in; (void)out_size;

    void *p_agg = nullptr, *p_deg = nullptr;
    cudaGetSymbolAddress(&p_agg, g_agg);
    cudaGetSymbolAddress(&p_deg, g_deg);

    constexpr int SMEM_LIN = 16384 * 4;                          //  64 KB
    constexpr int SMEM_L0  = 32768 * 4;                          // 128 KB
    constexpr int SMEM_L1  = (40960 + 16384) * 4;                // 224 KB
    cudaFuncSetAttribute(k_lin_in,   cudaFuncAttributeMaxDynamicSharedMemorySize, SMEM_LIN);
    cudaFuncSetAttribute(k_layer<0>, cudaFuncAttributeMaxDynamicSharedMemorySize, SMEM_L0);
    cudaFuncSetAttribute(k_layer<1>, cudaFuncAttributeMaxDynamicSharedMemorySize, SMEM_L1);

    const int grid = (NNODES + 127) / 128;  // 128 rows per 512-thread block

    cudaMemsetAsync(p_deg, 0, NNODES * sizeof(float));
    k_deg<<<592, 512>>>(ei);

    k_lin_in<<<grid, 512, SMEM_LIN>>>(x, W_in, b_in);

    cudaMemsetAsync(p_agg, 0, (size_t)NNODES * HIDDIM * sizeof(float));
    k_scatter<<<(NEDGES + 7) / 8, 256>>>(ei);
    k_layer<0><<<grid, 512, SMEM_L0>>>(W_self, W_neigh, nullptr, nullptr, nullptr);

    cudaMemsetAsync(p_agg, 0, (size_t)NNODES * HIDDIM * sizeof(float));
    k_scatter<<<(NEDGES + 7) / 8, 256>>>(ei);
    k_layer<1><<<grid, 512, SMEM_L1>>>(W_self + (size_t)128 * 128,
                                       W_neigh + (size_t)128 * 128,
                                       W_out, b_out, out);
}